// round 12
// baseline (speedup 1.0000x reference)
#include <cuda_runtime.h>

typedef unsigned long long ull;

#define HH 192
#define BB 16
#define NPIX (BB*2*HH*HH)

// ---------- packed f32x2 helpers (sm_103a) ----------
__device__ __forceinline__ ull pk2(float x, float y){ ull r; asm("mov.b64 %0,{%1,%2};":"=l"(r):"f"(x),"f"(y)); return r; }
__device__ __forceinline__ ull dup2(float x){ return pk2(x,x); }
__device__ __forceinline__ void unpk2(ull v, float&x, float&y){ asm("mov.b64 {%0,%1},%2;":"=f"(x),"=f"(y):"l"(v)); }
__device__ __forceinline__ ull ffma2(ull a, ull b, ull c){ ull d; asm("fma.rn.f32x2 %0,%1,%2,%3;":"=l"(d):"l"(a),"l"(b),"l"(c)); return d; }
__device__ __forceinline__ ull fmul2(ull a, ull b){ ull d; asm("mul.rn.f32x2 %0,%1,%2;":"=l"(d):"l"(a),"l"(b)); return d; }
__device__ __forceinline__ ull fadd2(ull a, ull b){ ull d; asm("add.rn.f32x2 %0,%1,%2;":"=l"(d):"l"(a),"l"(b)); return d; }

// ---------- constants ----------
// Conv stencils: kA=(fd00,fd01), kB=(fd10,fd02), kC=(fd11,fd20); each tap value
// duplicated into both lanes (lanes = pixel pair). Scaled by dx^-ord.
// Poly weights per k, duplicated lanes. pw01[k][i] = (w0[k][u=0][i], w0[k][u=1][i]).
struct ConstBlob {
  ulonglong2 kA[25], kB[25], kC[25];
  ulonglong2 pw01[2][12];
  ulonglong2 pw11[2][13];
  ull pwfd[2][14];
  ulonglong2 pb0d[2];       // .x=b0[k][0] .y=b0[k][1]
  ulonglong2 pb1d[2];
  ull pbfd[2];
  ulonglong2 gw0d[2][2];    // [k][off]: .x=u0 weight at idx k*6+1+off, .y=u1
  ulonglong2 gw1d[2][2];
  ull gwfd[2][2];
};

__constant__ ConstBlob cb;
__device__ ConstBlob g_stage;
__device__ __align__(16) float g_uh[NPIX];
__device__ __align__(16) float g_ua[NPIX];
__device__ __align__(16) float g_ub[NPIX];

__global__ void prep_kernel(const float* __restrict__ kern,
                            const float* __restrict__ w0, const float* __restrict__ b0,
                            const float* __restrict__ w1, const float* __restrict__ b1,
                            const float* __restrict__ wf, const float* __restrict__ bf)
{
  int t = threadIdx.x;
  const double dDX = 0.0327249;
  const float s1 = (float)(1.0/dDX);
  const float s2 = (float)(1.0/(dDX*dDX));
  const float sc[6] = {1.f, s1, s1, s2, s2, s2};
  if (t < 75) {
    int g = t/25, e = t%25;
    ulonglong2 v;
    v.x = dup2(kern[(2*g)*25 + e]   * sc[2*g]);
    v.y = dup2(kern[(2*g+1)*25 + e] * sc[2*g+1]);
    if (g == 0) g_stage.kA[e] = v;
    else if (g == 1) g_stage.kB[e] = v;
    else g_stage.kC[e] = v;
  }
  if (t == 0) {
    for (int k = 0; k < 2; k++) {
      for (int i = 0; i < 12; i++) {
        ulonglong2 a;
        a.x = dup2(w0[k*24 + i]);
        a.y = dup2(w0[k*24 + 12 + i]);
        g_stage.pw01[k][i] = a;
      }
      for (int i = 0; i < 13; i++) {
        ulonglong2 a;
        a.x = dup2(w1[k*26 + i]);
        a.y = dup2(w1[k*26 + 13 + i]);
        g_stage.pw11[k][i] = a;
      }
      for (int i = 0; i < 14; i++) g_stage.pwfd[k][i] = dup2(wf[k*14 + i]);
      { ulonglong2 a; a.x = dup2(b0[k*2+0]); a.y = dup2(b0[k*2+1]); g_stage.pb0d[k] = a; }
      { ulonglong2 a; a.x = dup2(b1[k*2+0]); a.y = dup2(b1[k*2+1]); g_stage.pb1d[k] = a; }
      g_stage.pbfd[k] = dup2(bf[k]);
      for (int o = 0; o < 2; o++) {
        int idx = k*6 + 1 + o;
        ulonglong2 a, c;
        a.x = dup2(w0[k*24 + idx]);      a.y = dup2(w0[k*24 + 12 + idx]);
        c.x = dup2(w1[k*26 + idx]);      c.y = dup2(w1[k*26 + 13 + idx]);
        g_stage.gw0d[k][o] = a;
        g_stage.gw1d[k][o] = c;
        g_stage.gwfd[k][o] = dup2(wf[k*14 + idx]);
      }
    }
  }
}

// out = ubase + coef*rhs(ueval).
// Block (16,6,2): tx = pixel-pair (32 px wide), ry = pixel row (6), c = channel.
// Lanes of every packed value = (pixel 2tx, pixel 2tx+1). Channel is warp-uniform.
// Cross-channel features / upwind deltas exchanged through smem.
__global__ __launch_bounds__(192, 7)
void rhs_step(const float* __restrict__ ue, const float* __restrict__ ub,
              float coef, float* __restrict__ out)
{
  __shared__ float tE[2][10][36];     // halo tile per channel
  __shared__ float tO[2][10][36];     // same tile shifted left by 1 float (odd-parity pairs)
  __shared__ ull   fsm[2][6][96];     // base features [ch][feat][pair]
  __shared__ ulonglong2 dsm[2][96];   // upwind deltas (d_k6p1, d_k6p2) per channel

  const int tx = threadIdx.x, ry = threadIdx.y, c = threadIdx.z;
  const int tid = tx + 16*ry + 96*c;
  const int w0_ = blockIdx.x*32, h0 = blockIdx.y*6, b = blockIdx.z;

  // ---- halo load: 720 floats (both channels) ----
  for (int e = tid; e < 720; e += 192) {
    int ch = e/360, rem = e%360;
    int r = rem/36, x = rem%36;
    int h = h0 + r - 2; if (h < 0) h += HH; if (h >= HH) h -= HH;
    int wc = w0_ + x - 2; if (wc < 0) wc += HH; if (wc >= HH) wc -= HH;
    float v = ue[((size_t)(b*2+ch)*HH + h)*HH + wc];
    tE[ch][r][x] = v;
    if (x > 0) tO[ch][r][x-1] = v;
  }
  __syncthreads();

  // ---- conv: 8 correlations for own channel, 2 pixels packed in lanes ----
  ull a0=0ull,a1=0ull,a2=0ull,a3=0ull,a4=0ull,a5=0ull,t6=0ull,t7=0ull;
  #pragma unroll
  for (int i = 0; i < 5; i++) {
    ull w[5];
    // pair at halo col 2tx+j: j even -> tE[2tx+j]; j odd -> tO[2tx+j-1]
    w[0] = *(const ull*)&tE[c][ry+i][2*tx + 0];
    w[1] = *(const ull*)&tO[c][ry+i][2*tx + 0];
    w[2] = *(const ull*)&tE[c][ry+i][2*tx + 2];
    w[3] = *(const ull*)&tO[c][ry+i][2*tx + 2];
    w[4] = *(const ull*)&tE[c][ry+i][2*tx + 4];
    #pragma unroll
    for (int j = 0; j < 5; j++) {
      const ulonglong2 kAe = cb.kA[i*5+j];
      const ulonglong2 kBe = cb.kB[i*5+j];
      const ulonglong2 kCe = cb.kC[i*5+j];
      a0 = ffma2(kAe.x, w[j], a0);
      a1 = ffma2(kAe.y, w[j], a1);
      a2 = ffma2(kBe.x, w[j], a2);
      a3 = ffma2(kBe.y, w[j], a3);
      a4 = ffma2(kCe.x, w[j], a4);
      a5 = ffma2(kCe.y, w[j], a5);
      t6 = ffma2(kAe.y, w[4-j], t6);                 // f01 = -t6 (width mirror)
      t7 = ffma2(cb.kB[(4-i)*5+j].x, w[j], t7);      // f10 = -t7 (height mirror)
    }
  }

  const int pairidx = ry*16 + tx;
  fsm[c][0][pairidx] = a0;
  fsm[c][1][pairidx] = a1;
  fsm[c][2][pairidx] = a2;
  fsm[c][3][pairidx] = a3;
  fsm[c][4][pairidx] = a4;
  fsm[c][5][pairidx] = a5;
  __syncthreads();

  // ---- poly k=c, lanes = pixel pair. X[0..5]=ch0 feats, X[6..11]=ch1 feats ----
  ull p2 = cb.pb0d[c].x, q2 = cb.pb0d[c].y, rl = cb.pb1d[c].x, sl = cb.pb1d[c].y, ol = cb.pbfd[c];
  #pragma unroll
  for (int ii = 0; ii < 12; ii++) {
    ull xd = fsm[ii/6][ii%6][pairidx];
    const ulonglong2 wa = cb.pw01[c][ii];
    const ulonglong2 wb = cb.pw11[c][ii];
    p2 = ffma2(wa.x, xd, p2);
    q2 = ffma2(wa.y, xd, q2);
    rl = ffma2(wb.x, xd, rl);
    sl = ffma2(wb.y, xd, sl);
    ol = ffma2(cb.pwfd[c][ii], xd, ol);
  }
  const ull wmx = cb.pw11[c][12].x, wmy = cb.pw11[c][12].y;
  ull m1 = fmul2(p2, q2);
  ull r2 = ffma2(wmx, m1, rl);
  ull s2 = ffma2(wmy, m1, sl);

  // analytic gradient wrt own-channel inputs (indices c*6+1, c*6+2)
  ull g2[2];
  #pragma unroll
  for (int o = 0; o < 2; o++) {
    const ulonglong2 ga = cb.gw0d[c][o];
    const ulonglong2 gc = cb.gw1d[c][o];
    ull dm1 = fadd2(fmul2(q2, ga.x), fmul2(p2, ga.y));
    ull dr  = ffma2(wmx, dm1, gc.x);
    ull ds  = ffma2(wmy, dm1, gc.y);
    ull dm2 = fadd2(fmul2(s2, dr), fmul2(r2, ds));
    ull g   = ffma2(cb.pwfd[c][12], dm1, cb.gwfd[c][o]);
    g2[o]   = ffma2(cb.pwfd[c][13], dm2, g);
  }
  // upwind deltas for own channel (per pixel lane)
  {
    float gA0, gA1, gB0, gB1, t6x, t6y, t7x, t7y, a1x, a1y, a2x, a2y;
    unpk2(g2[0], gA0, gA1);
    unpk2(g2[1], gB0, gB1);
    unpk2(t6, t6x, t6y);
    unpk2(t7, t7x, t7y);
    unpk2(a1, a1x, a1y);
    unpk2(a2, a2x, a2y);
    ulonglong2 dd;
    dd.x = pk2((gA0 > 0.f) ? 0.f : (-t6x - a1x), (gA1 > 0.f) ? 0.f : (-t6y - a1y));
    dd.y = pk2((gB0 > 0.f) ? 0.f : (-t7x - a2x), (gB1 > 0.f) ? 0.f : (-t7y - a2y));
    dsm[c][pairidx] = dd;
  }
  __syncthreads();

  const ulonglong2 dd0 = dsm[0][pairidx];   // deltas at X[1], X[2]
  const ulonglong2 dd1 = dsm[1][pairidx];   // deltas at X[7], X[8]

  // delta-update linear parts, finish poly
  {
    const ulonglong2 c1 = cb.pw01[c][1], c2 = cb.pw01[c][2], c7 = cb.pw01[c][7], c8 = cb.pw01[c][8];
    p2 = ffma2(c1.x, dd0.x, ffma2(c2.x, dd0.y, ffma2(c7.x, dd1.x, ffma2(c8.x, dd1.y, p2))));
    q2 = ffma2(c1.y, dd0.x, ffma2(c2.y, dd0.y, ffma2(c7.y, dd1.x, ffma2(c8.y, dd1.y, q2))));
  }
  {
    const ulonglong2 e1 = cb.pw11[c][1], e2 = cb.pw11[c][2], e7 = cb.pw11[c][7], e8 = cb.pw11[c][8];
    rl = ffma2(e1.x, dd0.x, ffma2(e2.x, dd0.y, ffma2(e7.x, dd1.x, ffma2(e8.x, dd1.y, rl))));
    sl = ffma2(e1.y, dd0.x, ffma2(e2.y, dd0.y, ffma2(e7.y, dd1.x, ffma2(e8.y, dd1.y, sl))));
  }
  ol = ffma2(cb.pwfd[c][1], dd0.x, ffma2(cb.pwfd[c][2], dd0.y,
       ffma2(cb.pwfd[c][7], dd1.x, ffma2(cb.pwfd[c][8], dd1.y, ol))));

  m1 = fmul2(p2, q2);
  r2 = ffma2(wmx, m1, rl);
  s2 = ffma2(wmy, m1, sl);
  ull m2 = fmul2(r2, s2);
  ull o2 = ffma2(cb.pwfd[c][12], m1, ol);
  o2 = ffma2(cb.pwfd[c][13], m2, o2);

  // ---- epilogue: packed pixel pair, 64-bit load/store ----
  const int h = h0 + ry, wc = w0_ + 2*tx;
  const size_t idx = ((size_t)(b*2 + c)*HH + h)*HH + wc;
  ull ubp = *(const ull*)&ub[idx];
  ull res = ffma2(dup2(coef), o2, ubp);
  *(ull*)&out[idx] = res;
}

extern "C" void kernel_launch(void* const* d_in, const int* in_sizes, int n_in,
                              void* d_out, int out_size)
{
  (void)in_sizes; (void)n_in; (void)out_size;
  const float* init = (const float*)d_in[0];
  const float* kern = (const float*)d_in[1];
  const float* w0   = (const float*)d_in[2];
  const float* b0   = (const float*)d_in[3];
  const float* w1   = (const float*)d_in[4];
  const float* b1   = (const float*)d_in[5];
  const float* wf   = (const float*)d_in[6];
  const float* bf   = (const float*)d_in[7];
  float* out = (float*)d_out;

  void *puh, *pua, *pub, *pstage;
  cudaGetSymbolAddress(&puh, g_uh);
  cudaGetSymbolAddress(&pua, g_ua);
  cudaGetSymbolAddress(&pub, g_ub);
  cudaGetSymbolAddress(&pstage, g_stage);

  prep_kernel<<<1, 128>>>(kern, w0, b0, w1, b1, wf, bf);
  cudaMemcpyToSymbolAsync(cb, pstage, sizeof(ConstBlob), 0, cudaMemcpyDeviceToDevice, 0);

  dim3 grid(HH/32, HH/6, BB);
  dim3 block(16, 6, 2);

  const float DT = 0.2f;
  const float* ucur = init;
  for (int s = 0; s < 5; s++) {
    float* un = (s == 4) ? out : ((s & 1) ? (float*)pub : (float*)pua);
    rhs_step<<<grid, block>>>(ucur, ucur, DT*0.5f, (float*)puh);
    rhs_step<<<grid, block>>>((float*)puh, ucur, DT, un);
    ucur = un;
  }
}

// round 13
// speedup vs baseline: 3.5415x; 3.5415x over previous
#include <cuda_runtime.h>

typedef unsigned long long ull;

#define HH 192
#define BB 16
#define NPIX (BB*2*HH*HH)

// ---------- packed f32x2 helpers (sm_103a) ----------
__device__ __forceinline__ ull pk2(float x, float y){ ull r; asm("mov.b64 %0,{%1,%2};":"=l"(r):"f"(x),"f"(y)); return r; }
__device__ __forceinline__ ull dup2(float x){ return pk2(x,x); }
__device__ __forceinline__ void unpk2(ull v, float&x, float&y){ asm("mov.b64 {%0,%1},%2;":"=f"(x),"=f"(y):"l"(v)); }
__device__ __forceinline__ ull ffma2(ull a, ull b, ull c){ ull d; asm("fma.rn.f32x2 %0,%1,%2,%3;":"=l"(d):"l"(a),"l"(b),"l"(c)); return d; }
__device__ __forceinline__ ull fmul2(ull a, ull b){ ull d; asm("mul.rn.f32x2 %0,%1,%2;":"=l"(d):"l"(a),"l"(b)); return d; }
__device__ __forceinline__ ull fadd2(ull a, ull b){ ull d; asm("add.rn.f32x2 %0,%1,%2;":"=l"(d):"l"(a),"l"(b)); return d; }

// ---------- packed constants, 16B-vectorized ----------
struct ConstBlob {
  ulonglong2 kp[3][25];  // kp[p][i*5+j] = (stencil 2p, stencil 2p+1) tap, lanes dup
  ulonglong2 w0p[12];    // .x = p weight(i), .y = q weight(i); lanes = poly k0,k1
  ulonglong2 w1p[13];    // .x = r, .y = s
  ulonglong2 b01;        // .x = b0(p), .y = b0(q)
  ulonglong2 b11;        // .x = b1(r), .y = b1(s)
  ulonglong2 gw0p[2];    // [off-1]; .x = u=0 pack, .y = u=1 pack
  ulonglong2 gw1p[2];
  ull wf[14];
  ull bf;
  ull gwf[2];
};

__constant__ ConstBlob cb;
__device__ ConstBlob g_stage;
__device__ float g_uh[NPIX];
__device__ float g_ua[NPIX];
__device__ float g_ub[NPIX];

__global__ void prep_kernel(const float* __restrict__ kern,
                            const float* __restrict__ w0, const float* __restrict__ b0,
                            const float* __restrict__ w1, const float* __restrict__ b1,
                            const float* __restrict__ wf, const float* __restrict__ bf)
{
  int t = threadIdx.x;
  const double dDX = 0.0327249;
  const float s1 = (float)(1.0/dDX);
  const float s2 = (float)(1.0/(dDX*dDX));
  const float sc[6] = {1.f, s1, s1, s2, s2, s2};
  if (t < 75) {
    int p = t/25, e = t%25;
    int d0 = 2*p, d1 = 2*p+1;
    ulonglong2 v;
    v.x = dup2(kern[d0*25 + e] * sc[d0]);
    v.y = dup2(kern[d1*25 + e] * sc[d1]);
    g_stage.kp[p][e] = v;
  }
  if (t == 0) {
    for (int i = 0; i < 12; i++) {
      ulonglong2 a;
      a.x = pk2(w0[i],    w0[24+i]);
      a.y = pk2(w0[12+i], w0[24+12+i]);
      g_stage.w0p[i] = a;
    }
    for (int i = 0; i < 13; i++) {
      ulonglong2 a;
      a.x = pk2(w1[i],    w1[26+i]);
      a.y = pk2(w1[13+i], w1[26+13+i]);
      g_stage.w1p[i] = a;
    }
    { ulonglong2 a; a.x = pk2(b0[0], b0[2]); a.y = pk2(b0[1], b0[3]); g_stage.b01 = a; }
    { ulonglong2 a; a.x = pk2(b1[0], b1[2]); a.y = pk2(b1[1], b1[3]); g_stage.b11 = a; }
    for (int i = 0; i < 14; i++) g_stage.wf[i] = pk2(wf[i], wf[14+i]);
    g_stage.bf = pk2(bf[0], bf[1]);
    for (int o = 0; o < 2; o++) {
      ulonglong2 a, c;
      a.x = pk2(w0[1+o],      w0[24 + 7+o]);
      a.y = pk2(w0[12 + 1+o], w0[24 + 12 + 7+o]);
      g_stage.gw0p[o] = a;
      c.x = pk2(w1[1+o],      w1[26 + 7+o]);
      c.y = pk2(w1[13 + 1+o], w1[26 + 13 + 7+o]);
      g_stage.gw1p[o] = c;
      g_stage.gwf[o] = pk2(wf[1+o], wf[14 + 7+o]);
    }
  }
}

// out = ubase + coef * rhs(ueval); 1 pixel/thread, 32x6 blocks, 7 blocks/SM.
// same_base != 0 means ub == ue, so the output base pair is tile[ty+2][tx+2]
// (saves two exposed-latency LDG at the end of every thread).
__global__ __launch_bounds__(192, 7)
void rhs_step(const float* __restrict__ ue, const float* __restrict__ ub,
              float coef, float* __restrict__ out, int same_base)
{
  __shared__ ull tile[10][36];   // (c0,c1) packed, rows h0-2 .. h0+7

  const int tx = threadIdx.x, ty = threadIdx.y;
  const int tid = ty*32 + tx;
  const int w0_ = blockIdx.x*32, h0 = blockIdx.y*6, b = blockIdx.z;

  const float* u0 = ue + (size_t)b*2*HH*HH;
  const float* u1 = u0 + HH*HH;

  #pragma unroll
  for (int e = tid; e < 10*36; e += 192) {
    int r = e/36, c = e%36;
    int h = h0 + r - 2; if (h < 0) h += HH; if (h >= HH) h -= HH;
    int w = w0_ + c - 2; if (w < 0) w += HH; if (w >= HH) w -= HH;
    tile[r][c] = pk2(u0[h*HH+w], u1[h*HH+w]);
  }
  __syncthreads();

  // ---- 6 base correlations + 2 mirrored (constants shared via vector loads) ----
  ull a0=0ull,a1=0ull,a2=0ull,a3=0ull,a4=0ull,a5=0ull,t6=0ull,t7=0ull;
  #pragma unroll
  for (int i = 0; i < 5; i++) {
    ull w[5];
    #pragma unroll
    for (int j = 0; j < 5; j++) w[j] = tile[ty+i][tx+j];
    #pragma unroll
    for (int j = 0; j < 5; j++) {
      const ulonglong2 k01 = cb.kp[0][i*5+j];
      const ulonglong2 k23 = cb.kp[1][i*5+j];
      const ulonglong2 k45 = cb.kp[2][i*5+j];
      a0 = ffma2(k01.x, w[j], a0);
      a1 = ffma2(k01.y, w[j], a1);
      a2 = ffma2(k23.x, w[j], a2);
      a3 = ffma2(k23.y, w[j], a3);
      a4 = ffma2(k45.x, w[j], a4);
      a5 = ffma2(k45.y, w[j], a5);
      // f01 = -sum k01tap(i,j)*w(i,4-j): width mirror
      t6 = ffma2(k01.y, w[4-j], t6);
      // f10 = -sum k10tap(i,j)*w(4-i,j): height mirror (const CSE across unroll)
      t7 = ffma2(cb.kp[1][(4-i)*5+j].x, w[j], t7);
    }
  }

  float X[12];
  unpk2(a0, X[0], X[6]); unpk2(a1, X[1], X[7]); unpk2(a2, X[2], X[8]);
  unpk2(a3, X[3], X[9]); unpk2(a4, X[4], X[10]); unpk2(a5, X[5], X[11]);
  float n6x, n6y, n7x, n7y;
  unpk2(t6, n6x, n6y);   // f01 = -n6
  unpk2(t7, n7x, n7y);   // f10 = -n7

  // ---- poly linear parts at base (lanes = poly k0,k1) ----
  ull p2 = cb.b01.x, q2 = cb.b01.y, rl = cb.b11.x, sl = cb.b11.y, ol = cb.bf;
  #pragma unroll
  for (int i = 0; i < 12; i++) {
    ull xd = dup2(X[i]);
    const ulonglong2 wa = cb.w0p[i];
    const ulonglong2 wb = cb.w1p[i];
    p2 = ffma2(wa.x, xd, p2);
    q2 = ffma2(wa.y, xd, q2);
    rl = ffma2(wb.x, xd, rl);
    sl = ffma2(wb.y, xd, sl);
    ol = ffma2(cb.wf[i], xd, ol);
  }
  const ulonglong2 wm = cb.w1p[12];   // m1 coefficients for (r,s)
  ull m1 = fmul2(p2, q2);
  ull r2 = ffma2(wm.x, m1, rl);
  ull s2 = ffma2(wm.y, m1, sl);

  // ---- analytic gradient at base: d(poly_k)/dX[k*6+off], off=1,2 ----
  ull g2[2];
  #pragma unroll
  for (int o = 0; o < 2; o++) {
    const ulonglong2 ga = cb.gw0p[o];
    const ulonglong2 gc = cb.gw1p[o];
    ull dm1 = fadd2(fmul2(q2, ga.x), fmul2(p2, ga.y));
    ull dr  = ffma2(wm.x, dm1, gc.x);
    ull ds  = ffma2(wm.y, dm1, gc.y);
    ull dm2 = fadd2(fmul2(s2, dr), fmul2(r2, ds));
    ull g   = ffma2(cb.wf[12], dm1, cb.gwf[o]);
    g2[o]   = ffma2(cb.wf[13], dm2, g);
  }
  float g01a, g01b, g10a, g10b;
  unpk2(g2[0], g01a, g01b);
  unpk2(g2[1], g10a, g10b);

  // upwind deltas (0 if keep base, else flipped - base); flipped = -n
  float d1 = (g01a > 0.f) ? 0.f : (-n6x - X[1]);
  float d7 = (g01b > 0.f) ? 0.f : (-n6y - X[7]);
  float d2 = (g10a > 0.f) ? 0.f : (-n7x - X[2]);
  float d8 = (g10b > 0.f) ? 0.f : (-n7y - X[8]);
  ull D1 = dup2(d1), D2 = dup2(d2), D7 = dup2(d7), D8 = dup2(d8);

  // ---- delta-update linear parts to Xsel, finish poly ----
  {
    const ulonglong2 c1 = cb.w0p[1], c2 = cb.w0p[2], c7 = cb.w0p[7], c8 = cb.w0p[8];
    p2 = ffma2(c1.x, D1, ffma2(c2.x, D2, ffma2(c7.x, D7, ffma2(c8.x, D8, p2))));
    q2 = ffma2(c1.y, D1, ffma2(c2.y, D2, ffma2(c7.y, D7, ffma2(c8.y, D8, q2))));
  }
  {
    const ulonglong2 c1 = cb.w1p[1], c2 = cb.w1p[2], c7 = cb.w1p[7], c8 = cb.w1p[8];
    rl = ffma2(c1.x, D1, ffma2(c2.x, D2, ffma2(c7.x, D7, ffma2(c8.x, D8, rl))));
    sl = ffma2(c1.y, D1, ffma2(c2.y, D2, ffma2(c7.y, D7, ffma2(c8.y, D8, sl))));
  }
  ol = ffma2(cb.wf[1], D1, ffma2(cb.wf[2], D2, ffma2(cb.wf[7], D7, ffma2(cb.wf[8], D8, ol))));

  m1 = fmul2(p2, q2);
  r2 = ffma2(wm.x, m1, rl);
  s2 = ffma2(wm.y, m1, sl);
  ull m2 = fmul2(r2, s2);
  ull o2 = ffma2(cb.wf[12], m1, ol);
  o2 = ffma2(cb.wf[13], m2, o2);

  // ---- epilogue: packed base + single FFMA2 ----
  const int h = h0 + ty, w = w0_ + tx;
  const size_t i0 = ((size_t)(b*2))*HH*HH + (size_t)h*HH + w;
  ull ubp;
  if (same_base) {
    ubp = tile[ty+2][tx+2];                 // ub == ue: center pair already in smem
  } else {
    ubp = pk2(ub[i0], ub[i0 + HH*HH]);
  }
  ull res = ffma2(dup2(coef), o2, ubp);
  float r0, r1;
  unpk2(res, r0, r1);
  out[i0]         = r0;
  out[i0 + HH*HH] = r1;
}

extern "C" void kernel_launch(void* const* d_in, const int* in_sizes, int n_in,
                              void* d_out, int out_size)
{
  (void)in_sizes; (void)n_in; (void)out_size;
  const float* init = (const float*)d_in[0];
  const float* kern = (const float*)d_in[1];
  const float* w0   = (const float*)d_in[2];
  const float* b0   = (const float*)d_in[3];
  const float* w1   = (const float*)d_in[4];
  const float* b1   = (const float*)d_in[5];
  const float* wf   = (const float*)d_in[6];
  const float* bf   = (const float*)d_in[7];
  float* out = (float*)d_out;

  void *puh, *pua, *pub, *pstage;
  cudaGetSymbolAddress(&puh, g_uh);
  cudaGetSymbolAddress(&pua, g_ua);
  cudaGetSymbolAddress(&pub, g_ub);
  cudaGetSymbolAddress(&pstage, g_stage);

  prep_kernel<<<1, 128>>>(kern, w0, b0, w1, b1, wf, bf);
  cudaMemcpyToSymbolAsync(cb, pstage, sizeof(ConstBlob), 0, cudaMemcpyDeviceToDevice, 0);

  dim3 grid(HH/32, HH/6, BB);
  dim3 block(32, 6);

  const float DT = 0.2f;
  const float* ucur = init;
  for (int s = 0; s < 5; s++) {
    float* un = (s == 4) ? out : ((s & 1) ? (float*)pub : (float*)pua);
    rhs_step<<<grid, block>>>(ucur, ucur, DT*0.5f, (float*)puh, 1);
    rhs_step<<<grid, block>>>((float*)puh, ucur, DT, un, 0);
    ucur = un;
  }
}

// round 15
// speedup vs baseline: 3.7568x; 1.0608x over previous
#include <cuda_runtime.h>

typedef unsigned long long ull;

#define HH 192
#define BB 16
#define NPIX (BB*2*HH*HH)

// ---------- packed f32x2 helpers (sm_103a) ----------
__device__ __forceinline__ ull pk2(float x, float y){ ull r; asm("mov.b64 %0,{%1,%2};":"=l"(r):"f"(x),"f"(y)); return r; }
__device__ __forceinline__ ull dup2(float x){ return pk2(x,x); }
__device__ __forceinline__ void unpk2(ull v, float&x, float&y){ asm("mov.b64 {%0,%1},%2;":"=f"(x),"=f"(y):"l"(v)); }
__device__ __forceinline__ ull ffma2(ull a, ull b, ull c){ ull d; asm("fma.rn.f32x2 %0,%1,%2,%3;":"=l"(d):"l"(a),"l"(b),"l"(c)); return d; }
__device__ __forceinline__ ull fmul2(ull a, ull b){ ull d; asm("mul.rn.f32x2 %0,%1,%2;":"=l"(d):"l"(a),"l"(b)); return d; }
__device__ __forceinline__ ull fadd2(ull a, ull b){ ull d; asm("add.rn.f32x2 %0,%1,%2;":"=l"(d):"l"(a),"l"(b)); return d; }

// ---------- packed constants, 16B-vectorized ----------
struct ConstBlob {
  ulonglong2 kp[3][25];  // kp[p][i*5+j] = (stencil 2p, stencil 2p+1) tap, lanes dup
  ulonglong2 w0p[12];    // .x = p weight(i), .y = q weight(i); lanes = poly k0,k1
  ulonglong2 w1p[13];    // .x = r, .y = s
  ulonglong2 b01;        // .x = b0(p), .y = b0(q)
  ulonglong2 b11;        // .x = b1(r), .y = b1(s)
  ulonglong2 gw0p[2];    // [off-1]; .x = u=0 pack, .y = u=1 pack
  ulonglong2 gw1p[2];
  ull wf[14];
  ull bf;
  ull gwf[2];
};

__constant__ ConstBlob cb;
__device__ ConstBlob g_stage;
__device__ float g_uh[NPIX];
__device__ float g_ua[NPIX];
__device__ float g_ub[NPIX];

__global__ void prep_kernel(const float* __restrict__ kern,
                            const float* __restrict__ w0, const float* __restrict__ b0,
                            const float* __restrict__ w1, const float* __restrict__ b1,
                            const float* __restrict__ wf, const float* __restrict__ bf)
{
  int t = threadIdx.x;
  const double dDX = 0.0327249;
  const float s1 = (float)(1.0/dDX);
  const float s2 = (float)(1.0/(dDX*dDX));
  const float sc[6] = {1.f, s1, s1, s2, s2, s2};
  if (t < 75) {
    int p = t/25, e = t%25;
    int d0 = 2*p, d1 = 2*p+1;
    ulonglong2 v;
    v.x = dup2(kern[d0*25 + e] * sc[d0]);
    v.y = dup2(kern[d1*25 + e] * sc[d1]);
    g_stage.kp[p][e] = v;
  }
  if (t == 0) {
    for (int i = 0; i < 12; i++) {
      ulonglong2 a;
      a.x = pk2(w0[i],    w0[24+i]);
      a.y = pk2(w0[12+i], w0[24+12+i]);
      g_stage.w0p[i] = a;
    }
    for (int i = 0; i < 13; i++) {
      ulonglong2 a;
      a.x = pk2(w1[i],    w1[26+i]);
      a.y = pk2(w1[13+i], w1[26+13+i]);
      g_stage.w1p[i] = a;
    }
    { ulonglong2 a; a.x = pk2(b0[0], b0[2]); a.y = pk2(b0[1], b0[3]); g_stage.b01 = a; }
    { ulonglong2 a; a.x = pk2(b1[0], b1[2]); a.y = pk2(b1[1], b1[3]); g_stage.b11 = a; }
    for (int i = 0; i < 14; i++) g_stage.wf[i] = pk2(wf[i], wf[14+i]);
    g_stage.bf = pk2(bf[0], bf[1]);
    for (int o = 0; o < 2; o++) {
      ulonglong2 a, c;
      a.x = pk2(w0[1+o],      w0[24 + 7+o]);
      a.y = pk2(w0[12 + 1+o], w0[24 + 12 + 7+o]);
      g_stage.gw0p[o] = a;
      c.x = pk2(w1[1+o],      w1[26 + 7+o]);
      c.y = pk2(w1[13 + 1+o], w1[26 + 13 + 7+o]);
      g_stage.gw1p[o] = c;
      g_stage.gwf[o] = pk2(wf[1+o], wf[14 + 7+o]);
    }
  }
}

// out = ubase + coef * rhs(ueval); 1 pixel/thread, 32x6 blocks, 7 blocks/SM.
// PDL: prologue (index math) runs overlapped with the previous kernel's tail;
// cudaGridDependencySynchronize() gates the first data-dependent load.
// same_base != 0 means ub == ue (output base pair comes from the smem tile).
__global__ __launch_bounds__(192, 7)
void rhs_step(const float* __restrict__ ue, const float* __restrict__ ub,
              float coef, float* __restrict__ out, int same_base)
{
  __shared__ ull tile[10][36];   // (c0,c1) packed, rows h0-2 .. h0+7

  const int tx = threadIdx.x, ty = threadIdx.y;
  const int tid = ty*32 + tx;
  const int w0_ = blockIdx.x*32, h0 = blockIdx.y*6, b = blockIdx.z;

  const float* u0 = ue + (size_t)b*2*HH*HH;
  const float* u1 = u0 + HH*HH;

  // precompute halo addresses (independent of upstream data)
  int rr[2], cc[2];
  #pragma unroll
  for (int q = 0; q < 2; q++) {
    int e = tid + q*192;
    int r = e/36, c = e%36;
    int hh = h0 + r - 2; if (hh < 0) hh += HH; if (hh >= HH) hh -= HH;
    int ww = w0_ + c - 2; if (ww < 0) ww += HH; if (ww >= HH) ww -= HH;
    rr[q] = (e < 360) ? (hh*HH + ww) : -1;
    cc[q] = e;
  }

  // wait for upstream kernel's writes to become visible
  cudaGridDependencySynchronize();

  #pragma unroll
  for (int q = 0; q < 2; q++) {
    if (rr[q] >= 0) {
      int e = cc[q];
      tile[e/36][e%36] = pk2(u0[rr[q]], u1[rr[q]]);
    }
  }
  __syncthreads();

  // ---- 6 base correlations + 2 mirrored (constants shared via vector loads) ----
  ull a0=0ull,a1=0ull,a2=0ull,a3=0ull,a4=0ull,a5=0ull,t6=0ull,t7=0ull;
  #pragma unroll
  for (int i = 0; i < 5; i++) {
    ull w[5];
    #pragma unroll
    for (int j = 0; j < 5; j++) w[j] = tile[ty+i][tx+j];
    #pragma unroll
    for (int j = 0; j < 5; j++) {
      const ulonglong2 k01 = cb.kp[0][i*5+j];
      const ulonglong2 k23 = cb.kp[1][i*5+j];
      const ulonglong2 k45 = cb.kp[2][i*5+j];
      a0 = ffma2(k01.x, w[j], a0);
      a1 = ffma2(k01.y, w[j], a1);
      a2 = ffma2(k23.x, w[j], a2);
      a3 = ffma2(k23.y, w[j], a3);
      a4 = ffma2(k45.x, w[j], a4);
      a5 = ffma2(k45.y, w[j], a5);
      // f01 = -sum k01tap(i,j)*w(i,4-j): width mirror
      t6 = ffma2(k01.y, w[4-j], t6);
      // f10 = -sum k10tap(i,j)*w(4-i,j): height mirror (const CSE across unroll)
      t7 = ffma2(cb.kp[1][(4-i)*5+j].x, w[j], t7);
    }
  }

  float X[12];
  unpk2(a0, X[0], X[6]); unpk2(a1, X[1], X[7]); unpk2(a2, X[2], X[8]);
  unpk2(a3, X[3], X[9]); unpk2(a4, X[4], X[10]); unpk2(a5, X[5], X[11]);
  float n6x, n6y, n7x, n7y;
  unpk2(t6, n6x, n6y);   // f01 = -n6
  unpk2(t7, n7x, n7y);   // f10 = -n7

  // ---- poly linear parts at base (lanes = poly k0,k1) ----
  ull p2 = cb.b01.x, q2 = cb.b01.y, rl = cb.b11.x, sl = cb.b11.y, ol = cb.bf;
  #pragma unroll
  for (int i = 0; i < 12; i++) {
    ull xd = dup2(X[i]);
    const ulonglong2 wa = cb.w0p[i];
    const ulonglong2 wb = cb.w1p[i];
    p2 = ffma2(wa.x, xd, p2);
    q2 = ffma2(wa.y, xd, q2);
    rl = ffma2(wb.x, xd, rl);
    sl = ffma2(wb.y, xd, sl);
    ol = ffma2(cb.wf[i], xd, ol);
  }
  const ulonglong2 wm = cb.w1p[12];   // m1 coefficients for (r,s)
  ull m1 = fmul2(p2, q2);
  ull r2 = ffma2(wm.x, m1, rl);
  ull s2 = ffma2(wm.y, m1, sl);

  // ---- analytic gradient at base: d(poly_k)/dX[k*6+off], off=1,2 ----
  ull g2[2];
  #pragma unroll
  for (int o = 0; o < 2; o++) {
    const ulonglong2 ga = cb.gw0p[o];
    const ulonglong2 gc = cb.gw1p[o];
    ull dm1 = fadd2(fmul2(q2, ga.x), fmul2(p2, ga.y));
    ull dr  = ffma2(wm.x, dm1, gc.x);
    ull ds  = ffma2(wm.y, dm1, gc.y);
    ull dm2 = fadd2(fmul2(s2, dr), fmul2(r2, ds));
    ull g   = ffma2(cb.wf[12], dm1, cb.gwf[o]);
    g2[o]   = ffma2(cb.wf[13], dm2, g);
  }
  float g01a, g01b, g10a, g10b;
  unpk2(g2[0], g01a, g01b);
  unpk2(g2[1], g10a, g10b);

  // upwind deltas (0 if keep base, else flipped - base); flipped = -n
  float d1 = (g01a > 0.f) ? 0.f : (-n6x - X[1]);
  float d7 = (g01b > 0.f) ? 0.f : (-n6y - X[7]);
  float d2 = (g10a > 0.f) ? 0.f : (-n7x - X[2]);
  float d8 = (g10b > 0.f) ? 0.f : (-n7y - X[8]);
  ull D1 = dup2(d1), D2 = dup2(d2), D7 = dup2(d7), D8 = dup2(d8);

  // ---- delta-update linear parts to Xsel, finish poly ----
  {
    const ulonglong2 c1 = cb.w0p[1], c2 = cb.w0p[2], c7 = cb.w0p[7], c8 = cb.w0p[8];
    p2 = ffma2(c1.x, D1, ffma2(c2.x, D2, ffma2(c7.x, D7, ffma2(c8.x, D8, p2))));
    q2 = ffma2(c1.y, D1, ffma2(c2.y, D2, ffma2(c7.y, D7, ffma2(c8.y, D8, q2))));
  }
  {
    const ulonglong2 c1 = cb.w1p[1], c2 = cb.w1p[2], c7 = cb.w1p[7], c8 = cb.w1p[8];
    rl = ffma2(c1.x, D1, ffma2(c2.x, D2, ffma2(c7.x, D7, ffma2(c8.x, D8, rl))));
    sl = ffma2(c1.y, D1, ffma2(c2.y, D2, ffma2(c7.y, D7, ffma2(c8.y, D8, sl))));
  }
  ol = ffma2(cb.wf[1], D1, ffma2(cb.wf[2], D2, ffma2(cb.wf[7], D7, ffma2(cb.wf[8], D8, ol))));

  m1 = fmul2(p2, q2);
  r2 = ffma2(wm.x, m1, rl);
  s2 = ffma2(wm.y, m1, sl);
  ull m2 = fmul2(r2, s2);
  ull o2 = ffma2(cb.wf[12], m1, ol);
  o2 = ffma2(cb.wf[13], m2, o2);

  // ---- epilogue: packed base + single FFMA2 ----
  const int h = h0 + ty, w = w0_ + tx;
  const size_t i0 = ((size_t)(b*2))*HH*HH + (size_t)h*HH + w;
  ull ubp;
  if (same_base) {
    ubp = tile[ty+2][tx+2];                 // ub == ue: center pair already in smem
  } else {
    ubp = pk2(ub[i0], ub[i0 + HH*HH]);
  }
  ull res = ffma2(dup2(coef), o2, ubp);
  float r0, r1;
  unpk2(res, r0, r1);
  out[i0]         = r0;
  out[i0 + HH*HH] = r1;
}

extern "C" void kernel_launch(void* const* d_in, const int* in_sizes, int n_in,
                              void* d_out, int out_size)
{
  (void)in_sizes; (void)n_in; (void)out_size;
  const float* init = (const float*)d_in[0];
  const float* kern = (const float*)d_in[1];
  const float* w0   = (const float*)d_in[2];
  const float* b0   = (const float*)d_in[3];
  const float* w1   = (const float*)d_in[4];
  const float* b1   = (const float*)d_in[5];
  const float* wf   = (const float*)d_in[6];
  const float* bf   = (const float*)d_in[7];
  float* out = (float*)d_out;

  void *puh, *pua, *pub, *pstage;
  cudaGetSymbolAddress(&puh, g_uh);
  cudaGetSymbolAddress(&pua, g_ua);
  cudaGetSymbolAddress(&pub, g_ub);
  cudaGetSymbolAddress(&pstage, g_stage);

  prep_kernel<<<1, 128>>>(kern, w0, b0, w1, b1, wf, bf);
  cudaMemcpyToSymbolAsync(cb, pstage, sizeof(ConstBlob), 0, cudaMemcpyDeviceToDevice, 0);

  dim3 grid(HH/32, HH/6, BB);
  dim3 block(32, 6);

  // PDL launch config: allow each rhs_step to start while the previous
  // stream node is draining (kernel gates data reads with
  // cudaGridDependencySynchronize()).
  cudaLaunchAttribute attrs[1];
  attrs[0].id = cudaLaunchAttributeProgrammaticStreamSerialization;
  attrs[0].val.programmaticStreamSerializationAllowed = 1;
  cudaLaunchConfig_t cfg = {};
  cfg.gridDim = grid;
  cfg.blockDim = block;
  cfg.dynamicSmemBytes = 0;
  cfg.stream = 0;
  cfg.attrs = attrs;
  cfg.numAttrs = 1;

  const float DT = 0.2f;
  const float* ucur = init;
  for (int s = 0; s < 5; s++) {
    float* un = (s == 4) ? out : ((s & 1) ? (float*)pub : (float*)pua);
    cudaLaunchKernelEx(&cfg, rhs_step, ucur, ucur, DT*0.5f, (float*)puh, 1);
    cudaLaunchKernelEx(&cfg, rhs_step, (const float*)puh, ucur, DT, un, 0);
    ucur = un;
  }
}